// round 10
// baseline (speedup 1.0000x reference)
#include <cuda_runtime.h>
#include <cstdint>
#include <cstddef>

#define NN 100000
#define EE 1600000
#define H 128
#define D 128
#define LN_EPS 1e-5f

#define EDGE_BLOCKS ((EE + 255) / 256)          // 6250
#define GEMM_BLOCKS ((NN + 127) / 128)          // 782
#define GEMM_HALF1  (GEMM_BLOCKS / 2)           // 391
#define GEMM_HALF2  (GEMM_BLOCKS - GEMM_HALF1)  // 391

// Scratch (static device globals — no allocations allowed)
__device__ float g_h0[(size_t)NN * H];    // GEMM output (residual source)
__device__ float g_act[(size_t)NN * H];   // post-LN/ReLU activations (layer-0 input)
__device__ float g_agg[(size_t)NN * H];   // layer-0 gather output (layer-1 input)
__device__ int   g_cnt[NN];               // per-dst degree
__device__ int   g_rowptr[NN + 1];        // CSR row pointers
__device__ int   g_cursor[NN];            // scatter cursors
__device__ int2  g_edge[EE];              // CSR: packed (src, weight-as-int)
__device__ int   g_is64;                  // edge_index dtype flag

// ---------------------------------------------------------------------------
// Detect int64 vs int32 edge_index (ids < 2^31 so int64 => high words zero).
// ---------------------------------------------------------------------------
__global__ void detect_kernel(const int* __restrict__ w) {
    __shared__ int s;
    if (threadIdx.x == 0) s = 0;
    __syncthreads();
    int acc = 0;
    for (int i = threadIdx.x; i < 2048; i += blockDim.x) acc |= w[2 * i + 1];
    if (acc) atomicOr(&s, 1);
    __syncthreads();
    if (threadIdx.x == 0) g_is64 = (s == 0) ? 1 : 0;
}

__device__ __forceinline__ void load_edge(const void* ei, int e, int& src, int& dst) {
    if (g_is64) {
        const long long* p = (const long long*)ei;
        src = (int)p[e];
        dst = (int)p[EE + e];
    } else {
        const int* p = (const int*)ei;
        src = p[e];
        dst = p[EE + e];
    }
}

// ---------------------------------------------------------------------------
// Block-level prefix scan of g_cnt -> g_rowptr / g_cursor.
// ---------------------------------------------------------------------------
__global__ void __launch_bounds__(1024) scan_kernel() {
    __shared__ int part[1024];
    const int t = threadIdx.x;
    const int per = (NN + 1023) / 1024;  // 98
    const int b = t * per;
    int s = 0;
    for (int i = 0; i < per; i++) {
        int idx = b + i;
        if (idx < NN) s += g_cnt[idx];
    }
    part[t] = s;
    __syncthreads();
    for (int o = 1; o < 1024; o <<= 1) {
        int v = (t >= o) ? part[t - o] : 0;
        __syncthreads();
        part[t] += v;
        __syncthreads();
    }
    int run = part[t] - s;  // exclusive prefix of this chunk
    for (int i = 0; i < per; i++) {
        int idx = b + i;
        if (idx < NN) {
            g_rowptr[idx] = run;
            g_cursor[idx] = run;
            run += g_cnt[idx];
        }
    }
    if (t == 1023) g_rowptr[NN] = EE;
}

// ---------------------------------------------------------------------------
// GEMM device body (low-smem: 16-wide W and X tiles staged per iteration).
// Computes rows [m0, m0+128); fused epilogue: h0 = h, act = relu(LN(h)).
// ---------------------------------------------------------------------------
struct GemmSmem {
    float sW[16 * 129];  // [kk][n]
    float sX[16 * 129];  // [kk][m]
};

__device__ __forceinline__ void gemm_body(
    GemmSmem& sm, int m0,
    const float* __restrict__ X, const float* __restrict__ W,
    const float* __restrict__ bias,
    const float* __restrict__ ln_s, const float* __restrict__ ln_b,
    float* __restrict__ h0, float* __restrict__ act) {
    const int tid = threadIdx.x;
    const int ty = tid >> 4, tx = tid & 15;

    float acc[8][8];
#pragma unroll
    for (int i = 0; i < 8; i++)
#pragma unroll
        for (int j = 0; j < 8; j++) acc[i][j] = 0.f;

    const float4* X4 = (const float4*)X;
    const float4* W4 = (const float4*)W;

    for (int k0 = 0; k0 < D; k0 += 16) {
        __syncthreads();
        // X tile: 128 rows x 16 k -> sX[kk][m]
        for (int i = tid; i < 512; i += 256) {
            int m = i >> 2, kq = i & 3;
            int row = m0 + m;
            float4 x = make_float4(0.f, 0.f, 0.f, 0.f);
            if (row < NN) x = X4[(size_t)row * (D / 4) + (k0 >> 2) + kq];
            int k = kq * 4;
            sm.sX[(k + 0) * 129 + m] = x.x;
            sm.sX[(k + 1) * 129 + m] = x.y;
            sm.sX[(k + 2) * 129 + m] = x.z;
            sm.sX[(k + 3) * 129 + m] = x.w;
        }
        // W tile: 128 n x 16 k -> sW[kk][n]
        for (int i = tid; i < 512; i += 256) {
            int n = i >> 2, kq = i & 3;
            float4 w = W4[(size_t)n * (D / 4) + (k0 >> 2) + kq];
            int k = kq * 4;
            sm.sW[(k + 0) * 129 + n] = w.x;
            sm.sW[(k + 1) * 129 + n] = w.y;
            sm.sW[(k + 2) * 129 + n] = w.z;
            sm.sW[(k + 3) * 129 + n] = w.w;
        }
        __syncthreads();
#pragma unroll
        for (int kk = 0; kk < 16; kk++) {
            float a[8], bv[8];
#pragma unroll
            for (int i = 0; i < 8; i++) a[i] = sm.sX[kk * 129 + ty * 8 + i];
#pragma unroll
            for (int j = 0; j < 8; j++) bv[j] = sm.sW[kk * 129 + tx * 8 + j];
#pragma unroll
            for (int i = 0; i < 8; i++)
#pragma unroll
                for (int j = 0; j < 8; j++) acc[i][j] += a[i] * bv[j];
        }
    }

    // Epilogue: bias + write h0 + LN + ReLU + write act.
    const int colb = tx * 8;
    float bv[8], sc[8], sb[8];
#pragma unroll
    for (int j = 0; j < 8; j++) {
        bv[j] = bias[colb + j];
        sc[j] = ln_s[colb + j];
        sb[j] = ln_b[colb + j];
    }
#pragma unroll
    for (int i = 0; i < 8; i++) {
        const int row = m0 + ty * 8 + i;
        float v[8];
        float s = 0.f, sq = 0.f;
#pragma unroll
        for (int j = 0; j < 8; j++) {
            v[j] = acc[i][j] + bv[j];
            s += v[j];
            sq += v[j] * v[j];
        }
#pragma unroll
        for (int o = 8; o > 0; o >>= 1) {
            s  += __shfl_xor_sync(0xFFFFFFFFu, s, o);
            sq += __shfl_xor_sync(0xFFFFFFFFu, sq, o);
        }
        const float mu  = s * (1.f / H);
        const float var = sq * (1.f / H) - mu * mu;
        const float rs  = rsqrtf(var + LN_EPS);
        if (row < NN) {
            float a[8];
#pragma unroll
            for (int j = 0; j < 8; j++)
                a[j] = fmaxf((v[j] - mu) * rs * sc[j] + sb[j], 0.f);
            float* ph = h0  + (size_t)row * H + colb;
            float* pa = act + (size_t)row * H + colb;
            *(float4*)(ph + 0) = make_float4(v[0], v[1], v[2], v[3]);
            *(float4*)(ph + 4) = make_float4(v[4], v[5], v[6], v[7]);
            *(float4*)(pa + 0) = make_float4(a[0], a[1], a[2], a[3]);
            *(float4*)(pa + 4) = make_float4(a[4], a[5], a[6], a[7]);
        }
    }
}

// ---------------------------------------------------------------------------
// Fused kernel 1: edge blocks do the degree histogram; the rest run GEMM
// on rows [0, GEMM_HALF1*128).
// ---------------------------------------------------------------------------
__global__ void __launch_bounds__(256, 2) fused_hist_gemm(
    const void* __restrict__ ei,
    const float* __restrict__ X, const float* __restrict__ W,
    const float* __restrict__ bias,
    const float* __restrict__ ln_s, const float* __restrict__ ln_b,
    float* __restrict__ h0, float* __restrict__ act) {
    __shared__ GemmSmem sm;
    if (blockIdx.x < EDGE_BLOCKS) {
        int e = blockIdx.x * 256 + threadIdx.x;
        if (e < EE) {
            int src, dst;
            load_edge(ei, e, src, dst);
            atomicAdd(&g_cnt[dst], 1);
        }
        return;
    }
    const int m0 = (blockIdx.x - EDGE_BLOCKS) * 128;
    gemm_body(sm, m0, X, W, bias, ln_s, ln_b, h0, act);
}

// ---------------------------------------------------------------------------
// Fused kernel 2: edge blocks scatter edges into CSR slots; the rest run
// GEMM on rows [GEMM_HALF1*128, NN).
// ---------------------------------------------------------------------------
__global__ void __launch_bounds__(256, 2) fused_scatter_gemm(
    const void* __restrict__ ei, const float* __restrict__ ef,
    const float* __restrict__ X, const float* __restrict__ W,
    const float* __restrict__ bias,
    const float* __restrict__ ln_s, const float* __restrict__ ln_b,
    float* __restrict__ h0, float* __restrict__ act) {
    __shared__ GemmSmem sm;
    if (blockIdx.x < EDGE_BLOCKS) {
        int e = blockIdx.x * 256 + threadIdx.x;
        if (e < EE) {
            int src, dst;
            load_edge(ei, e, src, dst);
            int pos = atomicAdd(&g_cursor[dst], 1);
            g_edge[pos] = make_int2(src, __float_as_int(ef[e]));
        }
        return;
    }
    const int m0 = (GEMM_HALF1 + blockIdx.x - EDGE_BLOCKS) * 128;
    gemm_body(sm, m0, X, W, bias, ln_s, ln_b, h0, act);
}

// ---------------------------------------------------------------------------
// CSR gather SpMM: one warp per dst row; register accumulation; no atomics.
// Packed int2 edges; 8 loads in flight. Optional fused residual+LN+ReLU.
// NOTE: in and out must be DISTINCT buffers (reads arbitrary rows of `h`).
// ---------------------------------------------------------------------------
__global__ void __launch_bounds__(256) gather_kernel(
    const float* __restrict__ h, const float* __restrict__ res,
    const float* __restrict__ scale, const float* __restrict__ bias,
    float* __restrict__ out) {
    const int warp = (blockIdx.x * 256 + threadIdx.x) >> 5;
    const int lane = threadIdx.x & 31;
    if (warp >= NN) return;

    int j = g_rowptr[warp];
    const int e = g_rowptr[warp + 1];
    float4 acc = make_float4(0.f, 0.f, 0.f, 0.f);
    const int col = lane * 4;

    for (; j + 8 <= e; j += 8) {
        int2 ed[8];
#pragma unroll
        for (int q = 0; q < 8; q++) ed[q] = g_edge[j + q];
        float4 v[8];
#pragma unroll
        for (int q = 0; q < 8; q++)
            v[q] = *(const float4*)(h + (size_t)ed[q].x * H + col);
#pragma unroll
        for (int q = 0; q < 8; q++) {
            const float wq = __int_as_float(ed[q].y);
            acc.x += v[q].x * wq;
            acc.y += v[q].y * wq;
            acc.z += v[q].z * wq;
            acc.w += v[q].w * wq;
        }
    }
    for (; j + 2 <= e; j += 2) {
        int2 e0 = g_edge[j], e1 = g_edge[j + 1];
        float4 v0 = *(const float4*)(h + (size_t)e0.x * H + col);
        float4 v1 = *(const float4*)(h + (size_t)e1.x * H + col);
        const float w0 = __int_as_float(e0.y), w1 = __int_as_float(e1.y);
        acc.x += v0.x * w0 + v1.x * w1;
        acc.y += v0.y * w0 + v1.y * w1;
        acc.z += v0.z * w0 + v1.z * w1;
        acc.w += v0.w * w0 + v1.w * w1;
    }
    if (j < e) {
        int2 e0 = g_edge[j];
        float4 v0 = *(const float4*)(h + (size_t)e0.x * H + col);
        const float w0 = __int_as_float(e0.y);
        acc.x += v0.x * w0;
        acc.y += v0.y * w0;
        acc.z += v0.z * w0;
        acc.w += v0.w * w0;
    }

    const size_t base = (size_t)warp * H + col;
    if (res) {
        float4 r = *(const float4*)(res + base);
        acc.x += r.x; acc.y += r.y; acc.z += r.z; acc.w += r.w;
        float s  = acc.x + acc.y + acc.z + acc.w;
        float sq = acc.x * acc.x + acc.y * acc.y + acc.z * acc.z + acc.w * acc.w;
#pragma unroll
        for (int o = 16; o > 0; o >>= 1) {
            s  += __shfl_xor_sync(0xFFFFFFFFu, s, o);
            sq += __shfl_xor_sync(0xFFFFFFFFu, sq, o);
        }
        const float mu  = s * (1.f / H);
        const float var = sq * (1.f / H) - mu * mu;
        const float rs  = rsqrtf(var + LN_EPS);
        float4 sc = *(const float4*)(scale + col);
        float4 bi = *(const float4*)(bias + col);
        acc.x = fmaxf((acc.x - mu) * rs * sc.x + bi.x, 0.f);
        acc.y = fmaxf((acc.y - mu) * rs * sc.y + bi.y, 0.f);
        acc.z = fmaxf((acc.z - mu) * rs * sc.z + bi.z, 0.f);
        acc.w = fmaxf((acc.w - mu) * rs * sc.w + bi.w, 0.f);
    }
    *(float4*)(out + base) = acc;
}

// ---------------------------------------------------------------------------
// Launch
// ---------------------------------------------------------------------------
extern "C" void kernel_launch(void* const* d_in, const int* in_sizes, int n_in,
                              void* d_out, int out_size) {
    const float* x  = (const float*)d_in[0];
    const void*  ei = d_in[1];
    const float* ef = (const float*)d_in[2];
    const float* w  = (const float*)d_in[3];
    const float* b  = (const float*)d_in[4];
    const float* ls = (const float*)d_in[5];
    const float* lb = (const float*)d_in[6];
    float* out = (float*)d_out;

    float *h0, *act, *agg;
    int* cnt;
    cudaGetSymbolAddress((void**)&h0,  g_h0);
    cudaGetSymbolAddress((void**)&act, g_act);
    cudaGetSymbolAddress((void**)&agg, g_agg);
    cudaGetSymbolAddress((void**)&cnt, g_cnt);

    detect_kernel<<<1, 256>>>((const int*)ei);
    cudaMemsetAsync(cnt, 0, NN * sizeof(int));

    // hist (edge blocks) overlapped with GEMM first half
    fused_hist_gemm<<<EDGE_BLOCKS + GEMM_HALF1, 256>>>(
        ei, x, w, b, ls, lb, h0, act);
    scan_kernel<<<1, 1024>>>();
    // scatter (edge blocks) overlapped with GEMM second half
    fused_scatter_gemm<<<EDGE_BLOCKS + GEMM_HALF2, 256>>>(
        ei, ef, x, w, b, ls, lb, h0, act);

    // Layer 0 gather (act -> agg), fused residual+LN1+ReLU epilogue
    gather_kernel<<<(NN * 32 + 255) / 256, 256>>>(act, h0, ls + H, lb + H, agg);
    // Layer 1 gather (agg -> out)
    gather_kernel<<<(NN * 32 + 255) / 256, 256>>>(agg, nullptr, nullptr, nullptr, out);
}

// round 11
// speedup vs baseline: 1.7443x; 1.7443x over previous
#include <cuda_runtime.h>
#include <cstdint>
#include <cstddef>

#define NN 100000
#define EE 1600000
#define H 128
#define D 128
#define LN_EPS 1e-5f
#define CAP 128                 // per-node edge bucket capacity

// Scratch (static device globals — no allocations allowed)
__device__ float g_h0[(size_t)NN * H];        // GEMM output (residual source)
__device__ float g_act[(size_t)NN * H];       // post-LN/ReLU activations
__device__ float g_agg[(size_t)NN * H];       // layer-0 gather output
__device__ int   g_cnt[NN];                   // per-dst degree (bucket fill)
__device__ int2  g_edge[(size_t)NN * CAP];    // bucket CSR: (src, weight-as-int)
__device__ int2  g_ovf_e[EE];                 // overflow: (src, dst)
__device__ float g_ovf_w[EE];                 // overflow: weight
__device__ int   g_novf;                      // overflow count
__device__ int   g_is64;                      // edge_index dtype flag

// ---------------------------------------------------------------------------
// Detect int64 vs int32 edge_index (ids < 2^31 so int64 => high words zero).
// ---------------------------------------------------------------------------
__global__ void detect_kernel(const int* __restrict__ w) {
    __shared__ int s;
    if (threadIdx.x == 0) s = 0;
    __syncthreads();
    int acc = 0;
    for (int i = threadIdx.x; i < 2048; i += blockDim.x) acc |= w[2 * i + 1];
    if (acc) atomicOr(&s, 1);
    __syncthreads();
    if (threadIdx.x == 0) g_is64 = (s == 0) ? 1 : 0;
}

__device__ __forceinline__ void load_edge(const void* ei, int e, int& src, int& dst) {
    if (g_is64) {
        const long long* p = (const long long*)ei;
        src = (int)p[e];
        dst = (int)p[EE + e];
    } else {
        const int* p = (const int*)ei;
        src = p[e];
        dst = p[EE + e];
    }
}

// ---------------------------------------------------------------------------
// One-pass bucket scatter: no histogram, no scan. Overflow -> spill list.
// ---------------------------------------------------------------------------
__global__ void __launch_bounds__(256) scatter_kernel(const void* __restrict__ ei,
                                                      const float* __restrict__ ef) {
    int e = blockIdx.x * 256 + threadIdx.x;
    if (e >= EE) return;
    int src, dst;
    load_edge(ei, e, src, dst);
    float w = ef[e];
    int pos = atomicAdd(&g_cnt[dst], 1);
    if (pos < CAP) {
        g_edge[(size_t)dst * CAP + pos] = make_int2(src, __float_as_int(w));
    } else {
        int op = atomicAdd(&g_novf, 1);
        g_ovf_e[op] = make_int2(src, dst);
        g_ovf_w[op] = w;
    }
}

// ---------------------------------------------------------------------------
// GEMM: h = X @ W^T + bias, fused epilogue writes BOTH:
//   h0  = h                      (residual source)
//   act = relu(layernorm(h))     (layer-0 input)
// W held fully in smem (74KB dynamic). 256 threads, 8x8 micro-tile.
// ---------------------------------------------------------------------------
#define GEMM_SMEM_FLOATS (D * (H + 1) + 16 * (H + 1))

__global__ void __launch_bounds__(256, 1) gemm_kernel(
    const float* __restrict__ X, const float* __restrict__ W,
    const float* __restrict__ bias,
    const float* __restrict__ ln_s, const float* __restrict__ ln_b,
    float* __restrict__ h0, float* __restrict__ act) {
    extern __shared__ float sm[];
    float* sWT = sm;               // [k][n], stride 129
    float* sXT = sm + D * (H + 1); // [kk][m], stride 129

    const int tid = threadIdx.x;
    const int m0 = blockIdx.x * 128;

    const float4* W4 = (const float4*)W;
    for (int i = tid; i < H * (D / 4); i += 256) {
        int n = i >> 5, kq = i & 31;
        float4 w = W4[i];
        int k = kq * 4;
        sWT[(k + 0) * 129 + n] = w.x;
        sWT[(k + 1) * 129 + n] = w.y;
        sWT[(k + 2) * 129 + n] = w.z;
        sWT[(k + 3) * 129 + n] = w.w;
    }

    const int ty = tid >> 4, tx = tid & 15;
    float acc[8][8];
#pragma unroll
    for (int i = 0; i < 8; i++)
#pragma unroll
        for (int j = 0; j < 8; j++) acc[i][j] = 0.f;

    const float4* X4 = (const float4*)X;
    for (int k0 = 0; k0 < D; k0 += 16) {
        __syncthreads();
        for (int i = tid; i < 512; i += 256) {
            int m = i >> 2, kq = i & 3;
            int row = m0 + m;
            float4 x = make_float4(0.f, 0.f, 0.f, 0.f);
            if (row < NN) x = X4[(size_t)row * (D / 4) + (k0 >> 2) + kq];
            int k = kq * 4;
            sXT[(k + 0) * 129 + m] = x.x;
            sXT[(k + 1) * 129 + m] = x.y;
            sXT[(k + 2) * 129 + m] = x.z;
            sXT[(k + 3) * 129 + m] = x.w;
        }
        __syncthreads();
#pragma unroll
        for (int kk = 0; kk < 16; kk++) {
            float a[8], bv[8];
#pragma unroll
            for (int i = 0; i < 8; i++) a[i] = sXT[kk * 129 + ty * 8 + i];
#pragma unroll
            for (int j = 0; j < 8; j++) bv[j] = sWT[(k0 + kk) * 129 + tx * 8 + j];
#pragma unroll
            for (int i = 0; i < 8; i++)
#pragma unroll
                for (int j = 0; j < 8; j++) acc[i][j] += a[i] * bv[j];
        }
    }

    // Epilogue: bias + write h0 + LN + ReLU + write act.
    const int colb = tx * 8;
    float bv[8], sc[8], sb[8];
#pragma unroll
    for (int j = 0; j < 8; j++) {
        bv[j] = bias[colb + j];
        sc[j] = ln_s[colb + j];
        sb[j] = ln_b[colb + j];
    }
#pragma unroll
    for (int i = 0; i < 8; i++) {
        const int row = m0 + ty * 8 + i;
        float v[8];
        float s = 0.f, sq = 0.f;
#pragma unroll
        for (int j = 0; j < 8; j++) {
            v[j] = acc[i][j] + bv[j];
            s += v[j];
            sq += v[j] * v[j];
        }
        // reduce across the 16 tx lanes (same ty => same half-warp)
#pragma unroll
        for (int o = 8; o > 0; o >>= 1) {
            s  += __shfl_xor_sync(0xFFFFFFFFu, s, o);
            sq += __shfl_xor_sync(0xFFFFFFFFu, sq, o);
        }
        const float mu  = s * (1.f / H);
        const float var = sq * (1.f / H) - mu * mu;
        const float rs  = rsqrtf(var + LN_EPS);
        if (row < NN) {
            float a[8];
#pragma unroll
            for (int j = 0; j < 8; j++)
                a[j] = fmaxf((v[j] - mu) * rs * sc[j] + sb[j], 0.f);
            float* ph = h0  + (size_t)row * H + colb;
            float* pa = act + (size_t)row * H + colb;
            *(float4*)(ph + 0) = make_float4(v[0], v[1], v[2], v[3]);
            *(float4*)(ph + 4) = make_float4(v[4], v[5], v[6], v[7]);
            *(float4*)(pa + 0) = make_float4(a[0], a[1], a[2], a[3]);
            *(float4*)(pa + 4) = make_float4(a[4], a[5], a[6], a[7]);
        }
    }
}

// ---------------------------------------------------------------------------
// Bucket gather SpMM: one warp per dst row; register accumulation; no atomics.
// Row i's edges live at g_edge[i*CAP .. i*CAP+cnt). Overflow replay per row
// (free when g_novf == 0). Optional fused residual+LN+ReLU epilogue.
// NOTE: in and out must be DISTINCT buffers (reads arbitrary rows of `h`).
// ---------------------------------------------------------------------------
__global__ void __launch_bounds__(256) gather_kernel(
    const float* __restrict__ h, const float* __restrict__ res,
    const float* __restrict__ scale, const float* __restrict__ bias,
    float* __restrict__ out) {
    const int row = (blockIdx.x * 256 + threadIdx.x) >> 5;
    const int lane = threadIdx.x & 31;
    if (row >= NN) return;

    const int deg = g_cnt[row];
    const int n = deg < CAP ? deg : CAP;
    const int2* eb = g_edge + (size_t)row * CAP;
    float4 acc = make_float4(0.f, 0.f, 0.f, 0.f);
    const int col = lane * 4;

    int j = 0;
    for (; j + 8 <= n; j += 8) {
        int2 ed[8];
#pragma unroll
        for (int q = 0; q < 8; q++) ed[q] = eb[j + q];
        float4 v[8];
#pragma unroll
        for (int q = 0; q < 8; q++)
            v[q] = *(const float4*)(h + (size_t)ed[q].x * H + col);
#pragma unroll
        for (int q = 0; q < 8; q++) {
            const float wq = __int_as_float(ed[q].y);
            acc.x += v[q].x * wq;
            acc.y += v[q].y * wq;
            acc.z += v[q].z * wq;
            acc.w += v[q].w * wq;
        }
    }
    for (; j + 2 <= n; j += 2) {
        int2 e0 = eb[j], e1 = eb[j + 1];
        float4 v0 = *(const float4*)(h + (size_t)e0.x * H + col);
        float4 v1 = *(const float4*)(h + (size_t)e1.x * H + col);
        const float w0 = __int_as_float(e0.y), w1 = __int_as_float(e1.y);
        acc.x += v0.x * w0 + v1.x * w1;
        acc.y += v0.y * w0 + v1.y * w1;
        acc.z += v0.z * w0 + v1.z * w1;
        acc.w += v0.w * w0 + v1.w * w1;
    }
    if (j < n) {
        int2 e0 = eb[j];
        float4 v0 = *(const float4*)(h + (size_t)e0.x * H + col);
        const float w0 = __int_as_float(e0.y);
        acc.x += v0.x * w0;
        acc.y += v0.y * w0;
        acc.z += v0.z * w0;
        acc.w += v0.w * w0;
    }

    // Overflow replay (cost zero when no row exceeded CAP).
    if (deg > CAP) {
        const int no = g_novf;
        for (int t = 0; t < no; t++) {
            int2 sd = g_ovf_e[t];
            if (sd.y == row) {
                const float wt = g_ovf_w[t];
                float4 v = *(const float4*)(h + (size_t)sd.x * H + col);
                acc.x += v.x * wt;
                acc.y += v.y * wt;
                acc.z += v.z * wt;
                acc.w += v.w * wt;
            }
        }
    }

    const size_t base = (size_t)row * H + col;
    if (res) {
        float4 r = *(const float4*)(res + base);
        acc.x += r.x; acc.y += r.y; acc.z += r.z; acc.w += r.w;
        float s  = acc.x + acc.y + acc.z + acc.w;
        float sq = acc.x * acc.x + acc.y * acc.y + acc.z * acc.z + acc.w * acc.w;
#pragma unroll
        for (int o = 16; o > 0; o >>= 1) {
            s  += __shfl_xor_sync(0xFFFFFFFFu, s, o);
            sq += __shfl_xor_sync(0xFFFFFFFFu, sq, o);
        }
        const float mu  = s * (1.f / H);
        const float var = sq * (1.f / H) - mu * mu;
        const float rs  = rsqrtf(var + LN_EPS);
        float4 sc = *(const float4*)(scale + col);
        float4 bi = *(const float4*)(bias + col);
        acc.x = fmaxf((acc.x - mu) * rs * sc.x + bi.x, 0.f);
        acc.y = fmaxf((acc.y - mu) * rs * sc.y + bi.y, 0.f);
        acc.z = fmaxf((acc.z - mu) * rs * sc.z + bi.z, 0.f);
        acc.w = fmaxf((acc.w - mu) * rs * sc.w + bi.w, 0.f);
    }
    *(float4*)(out + base) = acc;
}

// ---------------------------------------------------------------------------
// Launch
// ---------------------------------------------------------------------------
extern "C" void kernel_launch(void* const* d_in, const int* in_sizes, int n_in,
                              void* d_out, int out_size) {
    const float* x  = (const float*)d_in[0];
    const void*  ei = d_in[1];
    const float* ef = (const float*)d_in[2];
    const float* w  = (const float*)d_in[3];
    const float* b  = (const float*)d_in[4];
    const float* ls = (const float*)d_in[5];
    const float* lb = (const float*)d_in[6];
    float* out = (float*)d_out;

    float *h0, *act, *agg;
    int *cnt, *novf;
    cudaGetSymbolAddress((void**)&h0,   g_h0);
    cudaGetSymbolAddress((void**)&act,  g_act);
    cudaGetSymbolAddress((void**)&agg,  g_agg);
    cudaGetSymbolAddress((void**)&cnt,  g_cnt);
    cudaGetSymbolAddress((void**)&novf, g_novf);

    const int smem = GEMM_SMEM_FLOATS * (int)sizeof(float);
    cudaFuncSetAttribute(gemm_kernel, cudaFuncAttributeMaxDynamicSharedMemorySize, smem);

    detect_kernel<<<1, 256>>>((const int*)ei);
    cudaMemsetAsync(cnt, 0, NN * sizeof(int));
    cudaMemsetAsync(novf, 0, sizeof(int));

    // One-pass bucket CSR build (no hist, no scan)
    scatter_kernel<<<(EE + 255) / 256, 256>>>(ei, ef);

    // Dense path: GEMM with fused bias + LN0 + ReLU epilogue
    gemm_kernel<<<(NN + 127) / 128, 256, smem>>>(x, w, b, ls, lb, h0, act);

    // Layer 0 gather (act -> agg), fused residual+LN1+ReLU epilogue
    gather_kernel<<<(NN * 32 + 255) / 256, 256>>>(act, h0, ls + H, lb + H, agg);
    // Layer 1 gather (agg -> out)
    gather_kernel<<<(NN * 32 + 255) / 256, 256>>>(agg, nullptr, nullptr, nullptr, out);
}

// round 12
// speedup vs baseline: 1.9995x; 1.1463x over previous
#include <cuda_runtime.h>
#include <cstdint>
#include <cstddef>

#define NN 100000
#define EE 1600000
#define H 128
#define D 128
#define LN_EPS 1e-5f
#define CAP 128                 // per-node edge bucket capacity

// Scratch (static device globals — no allocations allowed)
__device__ float g_h0[(size_t)NN * H];        // GEMM output (residual source)
__device__ float g_act[(size_t)NN * H];       // post-LN/ReLU activations
__device__ float g_agg[(size_t)NN * H];       // layer-0 gather output
__device__ int   g_cnt[NN];                   // per-dst degree (bucket fill)
__device__ int2  g_edge[(size_t)NN * CAP];    // bucket CSR: (src, weight-as-int)
__device__ int2  g_ovf_e[EE];                 // overflow: (src, dst)
__device__ float g_ovf_w[EE];                 // overflow: weight
__device__ int   g_novf;                      // overflow count
__device__ int   g_is64;                      // edge_index dtype flag

// ---------------------------------------------------------------------------
// Detect int64 vs int32 edge_index (ids < 2^31 so int64 => high words zero).
// ---------------------------------------------------------------------------
__global__ void detect_kernel(const int* __restrict__ w) {
    __shared__ int s;
    if (threadIdx.x == 0) s = 0;
    __syncthreads();
    int acc = 0;
    for (int i = threadIdx.x; i < 2048; i += blockDim.x) acc |= w[2 * i + 1];
    if (acc) atomicOr(&s, 1);
    __syncthreads();
    if (threadIdx.x == 0) g_is64 = (s == 0) ? 1 : 0;
}

__device__ __forceinline__ void load_edge(const void* ei, int e, int& src, int& dst) {
    if (g_is64) {
        const long long* p = (const long long*)ei;
        src = (int)p[e];
        dst = (int)p[EE + e];
    } else {
        const int* p = (const int*)ei;
        src = p[e];
        dst = p[EE + e];
    }
}

// ---------------------------------------------------------------------------
// One-pass bucket scatter: no histogram, no scan. Overflow -> spill list.
// ---------------------------------------------------------------------------
__global__ void __launch_bounds__(256) scatter_kernel(const void* __restrict__ ei,
                                                      const float* __restrict__ ef) {
    int e = blockIdx.x * 256 + threadIdx.x;
    if (e >= EE) return;
    int src, dst;
    load_edge(ei, e, src, dst);
    float w = ef[e];
    int pos = atomicAdd(&g_cnt[dst], 1);
    if (pos < CAP) {
        g_edge[(size_t)dst * CAP + pos] = make_int2(src, __float_as_int(w));
    } else {
        int op = atomicAdd(&g_novf, 1);
        g_ovf_e[op] = make_int2(src, dst);
        g_ovf_w[op] = w;
    }
}

// ---------------------------------------------------------------------------
// tf32 tensor-core GEMM: h = X @ W^T + bias; fused epilogue writes
//   h0  = h                      (residual source)
//   act = relu(layernorm(h))     (layer-0 input)
// Block = 128x128 tile, 8 warps; warp w owns rows [16w,16w+16) x 128 cols.
// mma.sync.m16n8k8.row.col.f32.tf32.tf32.f32, fp32 accumulation.
// ---------------------------------------------------------------------------
#define SMX_STRIDE 132
#define GEMM_SMEM_BYTES (2 * 128 * SMX_STRIDE * 4)

__device__ __forceinline__ uint32_t f2tf32(float f) {
    uint32_t r;
    asm("cvt.rna.tf32.f32 %0, %1;" : "=r"(r) : "f"(f));
    return r;
}

__global__ void __launch_bounds__(256, 1) gemm_kernel(
    const float* __restrict__ X, const float* __restrict__ W,
    const float* __restrict__ bias,
    const float* __restrict__ ln_s, const float* __restrict__ ln_b,
    float* __restrict__ h0, float* __restrict__ act) {
    extern __shared__ uint32_t sm[];
    uint32_t* sX = sm;                       // [row][k], stride 132
    uint32_t* sW = sm + 128 * SMX_STRIDE;    // [n][k],   stride 132

    const int tid = threadIdx.x;
    const int m0 = blockIdx.x * 128;

    // Stage X tile (rows m0..m0+127, zero-padded) and full W, as tf32.
    const float4* X4 = (const float4*)X;
    const float4* W4 = (const float4*)W;
    for (int i = tid; i < 128 * 32; i += 256) {
        int row = i >> 5, q = i & 31;
        int grow = m0 + row;
        float4 x = make_float4(0.f, 0.f, 0.f, 0.f);
        if (grow < NN) x = X4[(size_t)grow * 32 + q];
        uint32_t* p = sX + row * SMX_STRIDE + q * 4;
        p[0] = f2tf32(x.x); p[1] = f2tf32(x.y); p[2] = f2tf32(x.z); p[3] = f2tf32(x.w);
        float4 w = W4[(size_t)row * 32 + q];
        uint32_t* pw = sW + row * SMX_STRIDE + q * 4;
        pw[0] = f2tf32(w.x); pw[1] = f2tf32(w.y); pw[2] = f2tf32(w.z); pw[3] = f2tf32(w.w);
    }
    __syncthreads();

    const int warp = tid >> 5, lane = tid & 31;
    const int quad = lane >> 2, tq = lane & 3;
    const int mb = warp * 16;

    float c[16][4];
#pragma unroll
    for (int f = 0; f < 16; f++)
#pragma unroll
        for (int q = 0; q < 4; q++) c[f][q] = 0.f;

#pragma unroll
    for (int ks = 0; ks < 16; ks++) {
        const int k0 = ks * 8;
        const uint32_t* xr0 = sX + (mb + quad) * SMX_STRIDE + k0 + tq;
        const uint32_t* xr1 = xr0 + 8 * SMX_STRIDE;
        uint32_t a0 = xr0[0], a1 = xr1[0], a2 = xr0[4], a3 = xr1[4];
#pragma unroll
        for (int f = 0; f < 16; f++) {
            const uint32_t* wr = sW + (f * 8 + quad) * SMX_STRIDE + k0 + tq;
            uint32_t b0 = wr[0], b1 = wr[4];
            asm volatile(
                "mma.sync.aligned.m16n8k8.row.col.f32.tf32.tf32.f32 "
                "{%0,%1,%2,%3}, {%4,%5,%6,%7}, {%8,%9}, {%0,%1,%2,%3};"
                : "+f"(c[f][0]), "+f"(c[f][1]), "+f"(c[f][2]), "+f"(c[f][3])
                : "r"(a0), "r"(a1), "r"(a2), "r"(a3), "r"(b0), "r"(b1));
        }
    }

    // Epilogue. Thread holds rows r0 = m0+mb+quad, r1 = r0+8;
    // cols n0 = f*8 + tq*2, n1 = n0+1 for each of 16 frags.
    float bv0[16], bv1[16], sc0[16], sc1[16], sb0[16], sb1[16];
#pragma unroll
    for (int f = 0; f < 16; f++) {
        int n0 = f * 8 + tq * 2;
        bv0[f] = bias[n0];  bv1[f] = bias[n0 + 1];
        sc0[f] = ln_s[n0];  sc1[f] = ln_s[n0 + 1];
        sb0[f] = ln_b[n0];  sb1[f] = ln_b[n0 + 1];
    }

    float s0 = 0.f, q0 = 0.f, s1 = 0.f, q1 = 0.f;
#pragma unroll
    for (int f = 0; f < 16; f++) {
        c[f][0] += bv0[f]; c[f][1] += bv1[f];
        c[f][2] += bv0[f]; c[f][3] += bv1[f];
        s0 += c[f][0] + c[f][1];
        q0 += c[f][0] * c[f][0] + c[f][1] * c[f][1];
        s1 += c[f][2] + c[f][3];
        q1 += c[f][2] * c[f][2] + c[f][3] * c[f][3];
    }
    // Reduce across the 4 lanes of the quad (lanes quad*4 .. quad*4+3).
#pragma unroll
    for (int o = 1; o < 4; o <<= 1) {
        s0 += __shfl_xor_sync(0xFFFFFFFFu, s0, o);
        q0 += __shfl_xor_sync(0xFFFFFFFFu, q0, o);
        s1 += __shfl_xor_sync(0xFFFFFFFFu, s1, o);
        q1 += __shfl_xor_sync(0xFFFFFFFFu, q1, o);
    }
    const float mu0 = s0 * (1.f / H);
    const float rs0 = rsqrtf(q0 * (1.f / H) - mu0 * mu0 + LN_EPS);
    const float mu1 = s1 * (1.f / H);
    const float rs1 = rsqrtf(q1 * (1.f / H) - mu1 * mu1 + LN_EPS);

    const int r0 = m0 + mb + quad;
    const int r1 = r0 + 8;
    if (r0 < NN) {
        float* ph = h0  + (size_t)r0 * H;
        float* pa = act + (size_t)r0 * H;
#pragma unroll
        for (int f = 0; f < 16; f++) {
            int n0 = f * 8 + tq * 2;
            *(float2*)(ph + n0) = make_float2(c[f][0], c[f][1]);
            float a0 = fmaxf((c[f][0] - mu0) * rs0 * sc0[f] + sb0[f], 0.f);
            float a1 = fmaxf((c[f][1] - mu0) * rs0 * sc1[f] + sb1[f], 0.f);
            *(float2*)(pa + n0) = make_float2(a0, a1);
        }
    }
    if (r1 < NN) {
        float* ph = h0  + (size_t)r1 * H;
        float* pa = act + (size_t)r1 * H;
#pragma unroll
        for (int f = 0; f < 16; f++) {
            int n0 = f * 8 + tq * 2;
            *(float2*)(ph + n0) = make_float2(c[f][2], c[f][3]);
            float a0 = fmaxf((c[f][2] - mu1) * rs1 * sc0[f] + sb0[f], 0.f);
            float a1 = fmaxf((c[f][3] - mu1) * rs1 * sc1[f] + sb1[f], 0.f);
            *(float2*)(pa + n0) = make_float2(a0, a1);
        }
    }
}

// ---------------------------------------------------------------------------
// Bucket gather SpMM: one warp per dst row; register accumulation; no atomics.
// Row i's edges live at g_edge[i*CAP .. i*CAP+cnt). Overflow replay per row
// (free when g_novf == 0). Optional fused residual+LN+ReLU epilogue.
// NOTE: in and out must be DISTINCT buffers (reads arbitrary rows of `h`).
// ---------------------------------------------------------------------------
__global__ void __launch_bounds__(256) gather_kernel(
    const float* __restrict__ h, const float* __restrict__ res,
    const float* __restrict__ scale, const float* __restrict__ bias,
    float* __restrict__ out) {
    const int row = (blockIdx.x * 256 + threadIdx.x) >> 5;
    const int lane = threadIdx.x & 31;
    if (row >= NN) return;

    const int deg = g_cnt[row];
    const int n = deg < CAP ? deg : CAP;
    const int2* eb = g_edge + (size_t)row * CAP;
    float4 acc = make_float4(0.f, 0.f, 0.f, 0.f);
    const int col = lane * 4;

    int j = 0;
    for (; j + 8 <= n; j += 8) {
        int2 ed[8];
#pragma unroll
        for (int q = 0; q < 8; q++) ed[q] = eb[j + q];
        float4 v[8];
#pragma unroll
        for (int q = 0; q < 8; q++)
            v[q] = *(const float4*)(h + (size_t)ed[q].x * H + col);
#pragma unroll
        for (int q = 0; q < 8; q++) {
            const float wq = __int_as_float(ed[q].y);
            acc.x += v[q].x * wq;
            acc.y += v[q].y * wq;
            acc.z += v[q].z * wq;
            acc.w += v[q].w * wq;
        }
    }
    for (; j + 2 <= n; j += 2) {
        int2 e0 = eb[j], e1 = eb[j + 1];
        float4 v0 = *(const float4*)(h + (size_t)e0.x * H + col);
        float4 v1 = *(const float4*)(h + (size_t)e1.x * H + col);
        const float w0 = __int_as_float(e0.y), w1 = __int_as_float(e1.y);
        acc.x += v0.x * w0 + v1.x * w1;
        acc.y += v0.y * w0 + v1.y * w1;
        acc.z += v0.z * w0 + v1.z * w1;
        acc.w += v0.w * w0 + v1.w * w1;
    }
    if (j < n) {
        int2 e0 = eb[j];
        float4 v0 = *(const float4*)(h + (size_t)e0.x * H + col);
        const float w0 = __int_as_float(e0.y);
        acc.x += v0.x * w0;
        acc.y += v0.y * w0;
        acc.z += v0.z * w0;
        acc.w += v0.w * w0;
    }

    // Overflow replay (cost zero when no row exceeded CAP).
    if (deg > CAP) {
        const int no = g_novf;
        for (int t = 0; t < no; t++) {
            int2 sd = g_ovf_e[t];
            if (sd.y == row) {
                const float wt = g_ovf_w[t];
                float4 v = *(const float4*)(h + (size_t)sd.x * H + col);
                acc.x += v.x * wt;
                acc.y += v.y * wt;
                acc.z += v.z * wt;
                acc.w += v.w * wt;
            }
        }
    }

    const size_t base = (size_t)row * H + col;
    if (res) {
        float4 r = *(const float4*)(res + base);
        acc.x += r.x; acc.y += r.y; acc.z += r.z; acc.w += r.w;
        float s  = acc.x + acc.y + acc.z + acc.w;
        float sq = acc.x * acc.x + acc.y * acc.y + acc.z * acc.z + acc.w * acc.w;
#pragma unroll
        for (int o = 16; o > 0; o >>= 1) {
            s  += __shfl_xor_sync(0xFFFFFFFFu, s, o);
            sq += __shfl_xor_sync(0xFFFFFFFFu, sq, o);
        }
        const float mu  = s * (1.f / H);
        const float var = sq * (1.f / H) - mu * mu;
        const float rs  = rsqrtf(var + LN_EPS);
        float4 sc = *(const float4*)(scale + col);
        float4 bi = *(const float4*)(bias + col);
        acc.x = fmaxf((acc.x - mu) * rs * sc.x + bi.x, 0.f);
        acc.y = fmaxf((acc.y - mu) * rs * sc.y + bi.y, 0.f);
        acc.z = fmaxf((acc.z - mu) * rs * sc.z + bi.z, 0.f);
        acc.w = fmaxf((acc.w - mu) * rs * sc.w + bi.w, 0.f);
    }
    *(float4*)(out + base) = acc;
}

// ---------------------------------------------------------------------------
// Launch
// ---------------------------------------------------------------------------
extern "C" void kernel_launch(void* const* d_in, const int* in_sizes, int n_in,
                              void* d_out, int out_size) {
    const float* x  = (const float*)d_in[0];
    const void*  ei = d_in[1];
    const float* ef = (const float*)d_in[2];
    const float* w  = (const float*)d_in[3];
    const float* b  = (const float*)d_in[4];
    const float* ls = (const float*)d_in[5];
    const float* lb = (const float*)d_in[6];
    float* out = (float*)d_out;

    float *h0, *act, *agg;
    int *cnt, *novf;
    cudaGetSymbolAddress((void**)&h0,   g_h0);
    cudaGetSymbolAddress((void**)&act,  g_act);
    cudaGetSymbolAddress((void**)&agg,  g_agg);
    cudaGetSymbolAddress((void**)&cnt,  g_cnt);
    cudaGetSymbolAddress((void**)&novf, g_novf);

    cudaFuncSetAttribute(gemm_kernel, cudaFuncAttributeMaxDynamicSharedMemorySize,
                         GEMM_SMEM_BYTES);

    detect_kernel<<<1, 256>>>((const int*)ei);
    cudaMemsetAsync(cnt, 0, NN * sizeof(int));
    cudaMemsetAsync(novf, 0, sizeof(int));

    // One-pass bucket CSR build (no hist, no scan)
    scatter_kernel<<<(EE + 255) / 256, 256>>>(ei, ef);

    // Dense path: tf32 tensor-core GEMM with fused bias + LN0 + ReLU epilogue
    gemm_kernel<<<(NN + 127) / 128, 256, GEMM_SMEM_BYTES>>>(x, w, b, ls, lb, h0, act);

    // Layer 0 gather (act -> agg), fused residual+LN1+ReLU epilogue
    gather_kernel<<<(NN * 32 + 255) / 256, 256>>>(act, h0, ls + H, lb + H, agg);
    // Layer 1 gather (agg -> out)
    gather_kernel<<<(NN * 32 + 255) / 256, 256>>>(agg, nullptr, nullptr, nullptr, out);
}